// round 9
// baseline (speedup 1.0000x reference)
#include <cuda_runtime.h>
#include <math.h>

#define HH 7           // heads per state (Fano plane points)
#define LL 7           // Fano lines
#define BPB 32         // states (b) per block
#define TPB (BPB * 7)  // 224 threads
// State stride 64 floats = 256B: rows 16B-aligned AND state offset == 0 mod 128B
// -> LDS.128/STS.128 everywhere with <=2-way conflicts (h*32B term only).
#define SQ_STRIDE 64
#define PR_STRIDE 8    // products staging stays exactly linear (conflict-free)

// Fano lines (0-based), packed 4 bits per line: li={0,0,0,1,1,2,2},
// lj={1,3,5,3,4,3,4}, lk={2,4,6,5,6,6,5}  (fixed constants in the reference)
#define LI_PACK 0x02211000u
#define LJ_PACK 0x04343531u
#define LK_PACK 0x05665642u

__device__ double g_qerr_sum = 0.0;
__device__ double g_fano_sum = 0.0;
__device__ unsigned g_count = 0;

// Reduce two fp32 values across the block in one pass (224 thr = 7 warps).
__inline__ __device__ void blockReduce2F(float v1, float v2, float& o1, float& o2) {
    __shared__ float s1[8], s2[8];
    int lane = threadIdx.x & 31;
    int wid  = threadIdx.x >> 5;
    #pragma unroll
    for (int o = 16; o > 0; o >>= 1) {
        v1 += __shfl_down_sync(0xffffffffu, v1, o);
        v2 += __shfl_down_sync(0xffffffffu, v2, o);
    }
    if (lane == 0) { s1[wid] = v1; s2[wid] = v2; }
    __syncthreads();
    if (wid == 0) {
        v1 = (lane < (TPB >> 5)) ? s1[lane] : 0.0f;
        v2 = (lane < (TPB >> 5)) ? s2[lane] : 0.0f;
        #pragma unroll
        for (int o = 4; o > 0; o >>= 1) {
            v1 += __shfl_down_sync(0xffffffffu, v1, o);
            v2 += __shfl_down_sync(0xffffffffu, v2, o);
        }
        o1 = v1; o2 = v2;
    }
}

// Branchless closed-form nearest E8 root. All 240 roots have |r|^2=2, so
// nearest = argmax<residual,root>, computed analytically from root structure.
__device__ __forceinline__ int e8_nearest(const float r[8], float root_out[8]) {
    float a[8];
    unsigned smask = 0;   // sign bits, bit k
    unsigned rmask = 0;   // sign bits, bit (7-k)  (root-list enumeration order)
    #pragma unroll
    for (int k = 0; k < 8; k++) {
        unsigned sb = __float_as_uint(r[k]) >> 31;
        smask |= sb << k;
        rmask |= sb << (7 - k);
        a[k] = fabsf(r[k]);
    }

    // --- max (tree) + first index achieving it ---
    float m01 = fmaxf(a[0], a[1]), m23 = fmaxf(a[2], a[3]);
    float m45 = fmaxf(a[4], a[5]), m67 = fmaxf(a[6], a[7]);
    float a1 = fmaxf(fmaxf(m01, m23), fmaxf(m45, m67));
    unsigned em = 0;
    #pragma unroll
    for (int k = 0; k < 8; k++) em |= (a[k] == a1) ? (1u << k) : 0u;
    int i1 = __ffs(em) - 1;

    // --- second max: exclude i1 (a[] >= 0, so -1 acts as -inf) ---
    float b0 = (i1 == 0) ? -1.0f : a[0], b1 = (i1 == 1) ? -1.0f : a[1];
    float b2 = (i1 == 2) ? -1.0f : a[2], b3 = (i1 == 3) ? -1.0f : a[3];
    float b4 = (i1 == 4) ? -1.0f : a[4], b5 = (i1 == 5) ? -1.0f : a[5];
    float b6 = (i1 == 6) ? -1.0f : a[6], b7 = (i1 == 7) ? -1.0f : a[7];
    float a2 = fmaxf(fmaxf(fmaxf(b0, b1), fmaxf(b2, b3)),
                     fmaxf(fmaxf(b4, b5), fmaxf(b6, b7)));
    unsigned em2 = 0;
    em2 |= (b0 == a2) ? 1u : 0u;        em2 |= (b1 == a2) ? 2u : 0u;
    em2 |= (b2 == a2) ? 4u : 0u;        em2 |= (b3 == a2) ? 8u : 0u;
    em2 |= (b4 == a2) ? 16u : 0u;       em2 |= (b5 == a2) ? 32u : 0u;
    em2 |= (b6 == a2) ? 64u : 0u;       em2 |= (b7 == a2) ? 128u : 0u;
    int i2 = __ffs(em2) - 1;

    // --- sum, min + first index achieving it, parity ---
    float s = ((a[0] + a[1]) + (a[2] + a[3])) + ((a[4] + a[5]) + (a[6] + a[7]));
    float n01 = fminf(a[0], a[1]), n23 = fminf(a[2], a[3]);
    float n45 = fminf(a[4], a[5]), n67 = fminf(a[6], a[7]);
    float amin = fminf(fminf(n01, n23), fminf(n45, n67));
    unsigned nm = 0;
    #pragma unroll
    for (int k = 0; k < 8; k++) nm |= (a[k] == amin) ? (1u << k) : 0u;
    int imin = __ffs(nm) - 1;

    unsigned par = __popc(smask) & 1u;

    float pairDot = a1 + a2;
    float halfDot = 0.5f * s - (par ? amin : 0.0f);
    bool usePair = pairDot >= halfDot;

    // --- pair index: i<j among {i1,i2}; sign bits from smask ---
    int i = min(i1, i2), j = max(i1, i2);
    int pidx = i * 7 - ((i * (i - 1)) >> 1) + (j - i - 1);
    unsigned si = (smask >> i) & 1u, sj = (smask >> j) & 1u;
    int idxPair = 4 * pidx + 2 * (int)si + (int)sj;

    // --- half index: flip sign of min component if parity odd ---
    unsigned hv = rmask ^ (par << (7 - imin));
    int idxHalf = 112 + (int)(hv >> 1);

    #pragma unroll
    for (int k = 0; k < 8; k++) {
        float sgn = ((smask >> k) & 1u) ? -1.0f : 1.0f;
        float pairRoot = ((k == i1) | (k == i2)) ? sgn : 0.0f;
        float halfRoot = ((hv >> (7 - k)) & 1u) ? -0.5f : 0.5f;
        root_out[k] = usePair ? pairRoot : halfRoot;
    }
    return usePair ? idxPair : idxHalf;
}

__device__ __forceinline__ void qmul(const float q[4], const float p[4], float o[4]) {
    o[0] = q[0]*p[0] - q[1]*p[1] - q[2]*p[2] - q[3]*p[3];
    o[1] = q[0]*p[1] + q[1]*p[0] + q[2]*p[3] - q[3]*p[2];
    o[2] = q[0]*p[2] - q[1]*p[3] + q[2]*p[0] + q[3]*p[1];
    o[3] = q[0]*p[3] + q[1]*p[2] - q[2]*p[1] + q[3]*p[0];
}

// Shared body; FULL=true -> no bounds predicates (block entirely in range).
template <bool FULL>
__device__ __forceinline__ void fused_body(
        const float* __restrict__ states,
        float* __restrict__ out,
        float* __restrict__ prod_out,
        float* __restrict__ align_out,
        int nrows, size_t off_idx, int rem,
        float* sq, float* prs, float& qe, float& fsv) {
    int tid = threadIdx.x;
    int row = blockIdx.x * TPB + tid;
    int b_local = tid / 7;
    int sub     = tid - b_local * 7;

    // ---------------- Phase 1: residual E8 quantization ----------------
    if (FULL || tid < rem) {
        float x[8];
        const float4* p = reinterpret_cast<const float4*>(states + (size_t)row * 8);
        float4 v0 = p[0], v1 = p[1];
        x[0] = v0.x; x[1] = v0.y; x[2] = v0.z; x[3] = v0.w;
        x[4] = v1.x; x[5] = v1.y; x[6] = v1.z; x[7] = v1.w;

        float res[8], root[8], qsum[8];
        #pragma unroll
        for (int k = 0; k < 8; k++) res[k] = x[k];

        int idx0 = e8_nearest(res, root);
        #pragma unroll
        for (int k = 0; k < 8; k++) { qsum[k] = root[k]; res[k] = x[k] - qsum[k]; }

        int idx1 = e8_nearest(res, root);
        #pragma unroll
        for (int k = 0; k < 8; k++) {
            qsum[k] += root[k];
            float d = x[k] - qsum[k];
            qe += d * d;
        }

        // smem: state b_local at 64-float stride, head sub at 8-float offset
        float4* sp = reinterpret_cast<float4*>(sq + b_local * SQ_STRIDE + sub * 8);
        sp[0] = make_float4(qsum[0], qsum[1], qsum[2], qsum[3]);
        sp[1] = make_float4(qsum[4], qsum[5], qsum[6], qsum[7]);

        out[off_idx + row]                 = (float)idx0;
        out[off_idx + (size_t)nrows + row] = (float)idx1;
    }
    __syncthreads();

    // ------- Coalesced q writeout (dense float4 wavefronts) --------------
    {
        size_t base_f = (size_t)blockIdx.x * TPB * 8;
        float4* qout = reinterpret_cast<float4*>(out + base_f);
        // slot s=tid: rl=s>>1, bl=rl/7, h=rl%7, k0=(s&1)*4;
        // slot s=tid+224: same h/k0, bl += 16 -> smem offset +1024 floats.
        int rl = tid >> 1;
        int bl = rl / 7;
        int h  = rl - bl * 7;
        int k0 = (tid & 1) << 2;
        const float4* sp0 = reinterpret_cast<const float4*>(sq + bl * SQ_STRIDE + h * 8 + k0);
        if (FULL || (tid * 4) < rem * 8)
            qout[tid] = sp0[0];
        if (FULL || ((tid + TPB) * 4) < rem * 8)
            qout[tid + TPB] = sp0[16 * SQ_STRIDE / 4];
    }

    // ---------------- Phase 2: Fano octonion alignment (from smem) ------
    if (FULL || tid < rem) {
        int sh = sub * 4;
        int hi = (int)((LI_PACK >> sh) & 7u);
        int hj = (int)((LJ_PACK >> sh) & 7u);
        int hk = (int)((LK_PACK >> sh) & 7u);
        const float* base = sq + b_local * SQ_STRIDE;
        const float4* av4 = reinterpret_cast<const float4*>(base + hi * 8);
        const float4* bv4 = reinterpret_cast<const float4*>(base + hj * 8);
        const float4* cv4 = reinterpret_cast<const float4*>(base + hk * 8);
        float4 aqv = av4[0], bqv = av4[1];
        float4 cqv = bv4[0], dqv = bv4[1];
        float4 cl  = cv4[0], ch  = cv4[1];

        float aq[4] = {aqv.x, aqv.y, aqv.z, aqv.w};
        float bq[4] = {bqv.x, bqv.y, bqv.z, bqv.w};
        float cq[4] = {cqv.x, cqv.y, cqv.z, cqv.w};
        float dq[4] = {dqv.x, dqv.y, dqv.z, dqv.w};
        float dconj[4] = {dq[0], -dq[1], -dq[2], -dq[3]};
        float cconj[4] = {cq[0], -cq[1], -cq[2], -cq[3]};
        float cv[8] = {cl.x, cl.y, cl.z, cl.w, ch.x, ch.y, ch.z, ch.w};

        float t1[4], t2[4], t3[4], t4[4], pr[8];
        qmul(aq, cq, t1);
        qmul(dconj, bq, t2);
        qmul(dq, aq, t3);
        qmul(bq, cconj, t4);

        float dot = 0.0f, np2 = 0.0f, nc2 = 0.0f;
        #pragma unroll
        for (int k = 0; k < 4; k++) {
            float plo = t1[k] - t2[k];
            float phi = t3[k] + t4[k];
            float clo = cv[k], chi = cv[4 + k];
            dot += plo * clo + phi * chi;
            np2 += plo * plo + phi * phi;
            nc2 += clo * clo + chi * chi;
            pr[k]     = plo;
            pr[4 + k] = phi;
        }
        // staged products: linear layout, 2x STS.128 (conflict-free readout)
        float4* pw = reinterpret_cast<float4*>(prs + tid * 8);
        pw[0] = make_float4(pr[0], pr[1], pr[2], pr[3]);
        pw[1] = make_float4(pr[4], pr[5], pr[6], pr[7]);

        float align = dot * rsqrtf(fmaxf(np2 * nc2, 1e-16f));
        align_out[(size_t)blockIdx.x * TPB + tid] = align;

        float ac = fminf(fmaxf(align, -1.0f), 1.0f);
        fsv = 1.0f - ac;
    }
    __syncthreads();

    // ------- Coalesced products writeout (linear smem, dense global) -----
    {
        size_t base_f = (size_t)blockIdx.x * TPB * 8;
        float* gp = prod_out + base_f + tid;
        #pragma unroll
        for (int jj = 0; jj < 8; jj++) {
            if (FULL || (tid + jj * TPB) < rem * 8)
                gp[jj * TPB] = prs[tid + jj * TPB];
        }
    }
}

__global__ void __launch_bounds__(TPB, 7)
fused_kernel(const float* __restrict__ states,
             float* __restrict__ out,
             float* __restrict__ prod_out,
             float* __restrict__ align_out,
             float* __restrict__ qerr_out,
             float* __restrict__ fano_out,
             int nrows, size_t off_idx,
             double inv_nq, double inv_nf,
             unsigned nblocks) {
    __shared__ float sq[BPB * SQ_STRIDE];    // 8192 B
    __shared__ float prs[TPB * PR_STRIDE];   // 7168 B

    int rem = nrows - blockIdx.x * TPB;
    float qe = 0.0f, fsv = 0.0f;

    if (rem >= TPB) {
        fused_body<true>(states, out, prod_out, align_out,
                         nrows, off_idx, rem, sq, prs, qe, fsv);
    } else {
        fused_body<false>(states, out, prod_out, align_out,
                          nrows, off_idx, rem, sq, prs, qe, fsv);
    }

    // ---------------- Reduction + last-block finalize ----------------
    float bq_, bf_;
    blockReduce2F(qe, fsv, bq_, bf_);

    __shared__ bool amLast;
    if (threadIdx.x == 0) {
        atomicAdd(&g_qerr_sum, (double)bq_);
        atomicAdd(&g_fano_sum, (double)bf_);
        __threadfence();
        unsigned done = atomicAdd(&g_count, 1u);
        amLast = (done == nblocks - 1);
    }
    __syncthreads();
    if (amLast && threadIdx.x == 0) {
        double tq = *((volatile double*)&g_qerr_sum);
        double tf = *((volatile double*)&g_fano_sum);
        *qerr_out = (float)(tq * inv_nq);
        double fl = tf * inv_nf * 0.5;
        if (fl < 0.0) fl = 0.0;
        if (fl > 1.0) fl = 1.0;
        *fano_out = (float)fl;
        g_qerr_sum = 0.0;
        g_fano_sum = 0.0;
        g_count = 0;
    }
}

extern "C" void kernel_launch(void* const* d_in, const int* in_sizes, int n_in,
                              void* d_out, int out_size) {
    const float* states = (const float*)d_in[0];
    // d_in[1] = roots; d_in[2..4] = fano line indices (fixed constants, baked in)

    int B = in_sizes[0] / (HH * 8);      // 65536
    int nrows = B * HH;                  // 458752 = 224 * 2048

    float* out = (float*)d_out;
    size_t off_idx   = (size_t)nrows * 8;                 // quantized_ste
    size_t off_qerr  = off_idx + 2 * (size_t)nrows;       // indices (2, B, H)
    size_t off_prod  = off_qerr + 1;                      // q_err scalar
    size_t off_align = off_prod + (size_t)B * LL * 8;     // products (B, L, 8)
    size_t off_fano  = off_align + (size_t)B * LL;        // alignments (B, L)

    unsigned nblocks = (unsigned)((nrows + TPB - 1) / TPB);   // 2048

    fused_kernel<<<nblocks, TPB>>>(states, out,
                                   out + off_prod, out + off_align,
                                   out + off_qerr, out + off_fano,
                                   nrows, off_idx,
                                   1.0 / ((double)nrows * 8.0),
                                   1.0 / ((double)B * (double)LL),
                                   nblocks);
}

// round 10
// speedup vs baseline: 1.0779x; 1.0779x over previous
#include <cuda_runtime.h>
#include <math.h>

#define HH 7           // heads per state (Fano plane points)
#define LL 7           // Fano lines
#define BPB 32         // states (b) per block
#define TPB (BPB * 7)  // 224 threads
#define SQ_STRIDE 57   // 7*8 floats per state +1 pad (R7-proven: scalar, conflict-free)

// Fano lines (0-based), packed 4 bits per line (verified in R9 pass):
#define LI_PACK 0x02211000u
#define LJ_PACK 0x04343531u
#define LK_PACK 0x05665642u

__device__ double g_qerr_sum = 0.0;
__device__ double g_fano_sum = 0.0;
__device__ unsigned g_count = 0;

// Reduce two fp32 values across the block in one pass (224 thr = 7 warps).
__inline__ __device__ void blockReduce2F(float v1, float v2, float& o1, float& o2) {
    __shared__ float s1[8], s2[8];
    int lane = threadIdx.x & 31;
    int wid  = threadIdx.x >> 5;
    #pragma unroll
    for (int o = 16; o > 0; o >>= 1) {
        v1 += __shfl_down_sync(0xffffffffu, v1, o);
        v2 += __shfl_down_sync(0xffffffffu, v2, o);
    }
    if (lane == 0) { s1[wid] = v1; s2[wid] = v2; }
    __syncthreads();
    if (wid == 0) {
        v1 = (lane < (TPB >> 5)) ? s1[lane] : 0.0f;
        v2 = (lane < (TPB >> 5)) ? s2[lane] : 0.0f;
        #pragma unroll
        for (int o = 4; o > 0; o >>= 1) {
            v1 += __shfl_down_sync(0xffffffffu, v1, o);
            v2 += __shfl_down_sync(0xffffffffu, v2, o);
        }
        o1 = v1; o2 = v2;
    }
}

// Branchless closed-form nearest E8 root. All 240 roots have |r|^2=2, so
// nearest = argmax<residual,root>, computed analytically from root structure.
__device__ __forceinline__ int e8_nearest(const float r[8], float root_out[8]) {
    float a[8];
    unsigned smask = 0;   // sign bits, bit k
    unsigned rmask = 0;   // sign bits, bit (7-k)  (root-list enumeration order)
    #pragma unroll
    for (int k = 0; k < 8; k++) {
        unsigned sb = __float_as_uint(r[k]) >> 31;
        smask |= sb << k;
        rmask |= sb << (7 - k);
        a[k] = fabsf(r[k]);
    }

    // --- max (tree) + first index achieving it ---
    float m01 = fmaxf(a[0], a[1]), m23 = fmaxf(a[2], a[3]);
    float m45 = fmaxf(a[4], a[5]), m67 = fmaxf(a[6], a[7]);
    float a1 = fmaxf(fmaxf(m01, m23), fmaxf(m45, m67));
    unsigned em = 0;
    #pragma unroll
    for (int k = 0; k < 8; k++) em |= (a[k] == a1) ? (1u << k) : 0u;
    int i1 = __ffs(em) - 1;

    // --- second max: exclude i1 (a[] >= 0, so -1 acts as -inf) ---
    float b0 = (i1 == 0) ? -1.0f : a[0], b1 = (i1 == 1) ? -1.0f : a[1];
    float b2 = (i1 == 2) ? -1.0f : a[2], b3 = (i1 == 3) ? -1.0f : a[3];
    float b4 = (i1 == 4) ? -1.0f : a[4], b5 = (i1 == 5) ? -1.0f : a[5];
    float b6 = (i1 == 6) ? -1.0f : a[6], b7 = (i1 == 7) ? -1.0f : a[7];
    float a2 = fmaxf(fmaxf(fmaxf(b0, b1), fmaxf(b2, b3)),
                     fmaxf(fmaxf(b4, b5), fmaxf(b6, b7)));
    unsigned em2 = 0;
    em2 |= (b0 == a2) ? 1u : 0u;        em2 |= (b1 == a2) ? 2u : 0u;
    em2 |= (b2 == a2) ? 4u : 0u;        em2 |= (b3 == a2) ? 8u : 0u;
    em2 |= (b4 == a2) ? 16u : 0u;       em2 |= (b5 == a2) ? 32u : 0u;
    em2 |= (b6 == a2) ? 64u : 0u;       em2 |= (b7 == a2) ? 128u : 0u;
    int i2 = __ffs(em2) - 1;

    // --- sum, min + first index achieving it, parity ---
    float s = ((a[0] + a[1]) + (a[2] + a[3])) + ((a[4] + a[5]) + (a[6] + a[7]));
    float n01 = fminf(a[0], a[1]), n23 = fminf(a[2], a[3]);
    float n45 = fminf(a[4], a[5]), n67 = fminf(a[6], a[7]);
    float amin = fminf(fminf(n01, n23), fminf(n45, n67));
    unsigned nm = 0;
    #pragma unroll
    for (int k = 0; k < 8; k++) nm |= (a[k] == amin) ? (1u << k) : 0u;
    int imin = __ffs(nm) - 1;

    unsigned par = __popc(smask) & 1u;

    float pairDot = a1 + a2;
    float halfDot = 0.5f * s - (par ? amin : 0.0f);
    bool usePair = pairDot >= halfDot;

    // --- pair index: i<j among {i1,i2}; sign bits from smask ---
    int i = min(i1, i2), j = max(i1, i2);
    int pidx = i * 7 - ((i * (i - 1)) >> 1) + (j - i - 1);
    unsigned si = (smask >> i) & 1u, sj = (smask >> j) & 1u;
    int idxPair = 4 * pidx + 2 * (int)si + (int)sj;

    // --- half index: flip sign of min component if parity odd ---
    unsigned hv = rmask ^ (par << (7 - imin));
    int idxHalf = 112 + (int)(hv >> 1);

    #pragma unroll
    for (int k = 0; k < 8; k++) {
        float sgn = ((smask >> k) & 1u) ? -1.0f : 1.0f;
        float pairRoot = ((k == i1) | (k == i2)) ? sgn : 0.0f;
        float halfRoot = ((hv >> (7 - k)) & 1u) ? -0.5f : 0.5f;
        root_out[k] = usePair ? pairRoot : halfRoot;
    }
    return usePair ? idxPair : idxHalf;
}

__device__ __forceinline__ void qmul(const float q[4], const float p[4], float o[4]) {
    o[0] = q[0]*p[0] - q[1]*p[1] - q[2]*p[2] - q[3]*p[3];
    o[1] = q[0]*p[1] + q[1]*p[0] + q[2]*p[3] - q[3]*p[2];
    o[2] = q[0]*p[2] - q[1]*p[3] + q[2]*p[0] + q[3]*p[1];
    o[3] = q[0]*p[3] + q[1]*p[2] - q[2]*p[1] + q[3]*p[0];
}

// Shared body; FULL=true -> no bounds predicates + fast product stores.
template <bool FULL>
__device__ __forceinline__ void fused_body(
        const float* __restrict__ states,
        float* __restrict__ out,
        float* __restrict__ prod_out,
        float* __restrict__ align_out,
        int nrows, size_t off_idx, int rem,
        float* sq, float* nbuf, float& qe, float& fsv) {
    int tid = threadIdx.x;
    int row = blockIdx.x * TPB + tid;
    int b_local = tid / 7;
    int sub     = tid - b_local * 7;

    // ---------------- Phase 1: residual E8 quantization ----------------
    if (FULL || tid < rem) {
        float x[8];
        const float4* p = reinterpret_cast<const float4*>(states + (size_t)row * 8);
        float4 v0 = p[0], v1 = p[1];
        x[0] = v0.x; x[1] = v0.y; x[2] = v0.z; x[3] = v0.w;
        x[4] = v1.x; x[5] = v1.y; x[6] = v1.z; x[7] = v1.w;

        float res[8], root[8], qsum[8];
        #pragma unroll
        for (int k = 0; k < 8; k++) res[k] = x[k];

        int idx0 = e8_nearest(res, root);
        #pragma unroll
        for (int k = 0; k < 8; k++) { qsum[k] = root[k]; res[k] = x[k] - qsum[k]; }

        int idx1 = e8_nearest(res, root);
        #pragma unroll
        for (int k = 0; k < 8; k++) {
            qsum[k] += root[k];
            float d = x[k] - qsum[k];
            qe += d * d;
        }

        float* sp = sq + b_local * SQ_STRIDE + sub * 8;
        #pragma unroll
        for (int k = 0; k < 8; k++) sp[k] = qsum[k];

        out[off_idx + row]                 = (float)idx0;
        out[off_idx + (size_t)nrows + row] = (float)idx1;
    }
    __syncthreads();

    // ------- Coalesced q writeout from smem (float4-dense, R7 scheme) ----
    {
        size_t base_f = (size_t)blockIdx.x * TPB * 8;
        float4* qout = reinterpret_cast<float4*>(out + base_f);
        int rl0 = tid >> 1;
        int bl0 = rl0 / 7;
        int h0  = rl0 - bl0 * 7;
        int k0  = (tid & 1) << 2;
        const float* sp0 = sq + bl0 * SQ_STRIDE + h0 * 8 + k0;
        if (FULL || (tid * 4) < rem * 8)
            qout[tid] = make_float4(sp0[0], sp0[1], sp0[2], sp0[3]);
        const float* sp1 = sp0 + 16 * SQ_STRIDE;
        if (FULL || ((tid + TPB) * 4) < rem * 8)
            qout[tid + TPB] = make_float4(sp1[0], sp1[1], sp1[2], sp1[3]);
    }

    // ---------------- Phase 2: Fano octonion alignment (from smem) ------
    float pr[8];
    if (FULL || tid < rem) {
        int sh = sub * 4;
        int hi = (int)((LI_PACK >> sh) & 7u);
        int hj = (int)((LJ_PACK >> sh) & 7u);
        int hk = (int)((LK_PACK >> sh) & 7u);
        const float* base = sq + b_local * SQ_STRIDE;
        const float* av = base + hi * 8;
        const float* bv = base + hj * 8;
        const float* cv = base + hk * 8;

        float aq[4] = {av[0], av[1], av[2], av[3]};
        float bq[4] = {av[4], av[5], av[6], av[7]};
        float cq[4] = {bv[0], bv[1], bv[2], bv[3]};
        float dq[4] = {bv[4], bv[5], bv[6], bv[7]};
        float dconj[4] = {dq[0], -dq[1], -dq[2], -dq[3]};
        float cconj[4] = {cq[0], -cq[1], -cq[2], -cq[3]};

        float t1[4], t2[4], t3[4], t4[4];
        qmul(aq, cq, t1);
        qmul(dconj, bq, t2);
        qmul(dq, aq, t3);
        qmul(bq, cconj, t4);

        float dot = 0.0f, np2 = 0.0f, nc2 = 0.0f;
        #pragma unroll
        for (int k = 0; k < 4; k++) {
            float plo = t1[k] - t2[k];
            float phi = t3[k] + t4[k];
            float clo = cv[k], chi = cv[4 + k];
            dot += plo * clo + phi * chi;
            np2 += plo * plo + phi * phi;
            nc2 += clo * clo + chi * chi;
            pr[k]     = plo;
            pr[4 + k] = phi;
        }
        float align = dot * rsqrtf(fmaxf(np2 * nc2, 1e-16f));
        align_out[(size_t)blockIdx.x * TPB + tid] = align;

        float ac = fminf(fmaxf(align, -1.0f), 1.0f);
        fsv = 1.0f - ac;

        // publish first 3 product floats for left neighbor's packed store
        float* nb = nbuf + tid * 3;
        nb[0] = pr[0]; nb[1] = pr[1]; nb[2] = pr[2];
    }
    __syncthreads();

    // ------- Products writeout --------------------------------------------
    // Global region for this block: gp[0..1792). gp itself is 4B-aligned only
    // (off_prod is odd), but gp+3 is 16B-aligned -> two dense STG.128/thread.
    {
        float* gp = prod_out + (size_t)blockIdx.x * TPB * 8;
        if (FULL) {
            float4* g4 = reinterpret_cast<float4*>(gp + 3);
            // slot 2t: own elems 3..6
            g4[2 * tid] = make_float4(pr[3], pr[4], pr[5], pr[6]);
            // slot 2t+1: own elem 7 + neighbor (tid+1) elems 0..2
            if (tid < TPB - 1) {
                const float* nb = nbuf + (tid + 1) * 3;
                g4[2 * tid + 1] = make_float4(pr[7], nb[0], nb[1], nb[2]);
            }
            if (tid == 0)       { gp[0] = pr[0]; gp[1] = pr[1]; gp[2] = pr[2]; }
            if (tid == TPB - 1) { gp[TPB * 8 - 1] = pr[7]; }
        } else {
            if (tid < rem) {
                float* pw = gp + tid * 8;
                #pragma unroll
                for (int k = 0; k < 8; k++) pw[k] = pr[k];
            }
        }
    }
}

__global__ void __launch_bounds__(TPB, 7)
fused_kernel(const float* __restrict__ states,
             float* __restrict__ out,
             float* __restrict__ prod_out,
             float* __restrict__ align_out,
             float* __restrict__ qerr_out,
             float* __restrict__ fano_out,
             int nrows, size_t off_idx,
             double inv_nq, double inv_nf,
             unsigned nblocks) {
    __shared__ float sq[BPB * SQ_STRIDE];   // 7296 B
    __shared__ float nbuf[TPB * 3];         // 2688 B (neighbor handoff)

    int rem = nrows - blockIdx.x * TPB;
    float qe = 0.0f, fsv = 0.0f;

    if (rem >= TPB) {
        fused_body<true>(states, out, prod_out, align_out,
                         nrows, off_idx, rem, sq, nbuf, qe, fsv);
    } else {
        fused_body<false>(states, out, prod_out, align_out,
                          nrows, off_idx, rem, sq, nbuf, qe, fsv);
    }

    // ---------------- Reduction + last-block finalize ----------------
    float bq_, bf_;
    blockReduce2F(qe, fsv, bq_, bf_);

    __shared__ bool amLast;
    if (threadIdx.x == 0) {
        atomicAdd(&g_qerr_sum, (double)bq_);
        atomicAdd(&g_fano_sum, (double)bf_);
        __threadfence();
        unsigned done = atomicAdd(&g_count, 1u);
        amLast = (done == nblocks - 1);
    }
    __syncthreads();
    if (amLast && threadIdx.x == 0) {
        double tq = *((volatile double*)&g_qerr_sum);
        double tf = *((volatile double*)&g_fano_sum);
        *qerr_out = (float)(tq * inv_nq);
        double fl = tf * inv_nf * 0.5;
        if (fl < 0.0) fl = 0.0;
        if (fl > 1.0) fl = 1.0;
        *fano_out = (float)fl;
        g_qerr_sum = 0.0;
        g_fano_sum = 0.0;
        g_count = 0;
    }
}

extern "C" void kernel_launch(void* const* d_in, const int* in_sizes, int n_in,
                              void* d_out, int out_size) {
    const float* states = (const float*)d_in[0];
    // d_in[1] = roots; d_in[2..4] = fano line indices (fixed constants, baked in)

    int B = in_sizes[0] / (HH * 8);      // 65536
    int nrows = B * HH;                  // 458752 = 224 * 2048

    float* out = (float*)d_out;
    size_t off_idx   = (size_t)nrows * 8;                 // quantized_ste
    size_t off_qerr  = off_idx + 2 * (size_t)nrows;       // indices (2, B, H)
    size_t off_prod  = off_qerr + 1;                      // q_err scalar
    size_t off_align = off_prod + (size_t)B * LL * 8;     // products (B, L, 8)
    size_t off_fano  = off_align + (size_t)B * LL;        // alignments (B, L)

    unsigned nblocks = (unsigned)((nrows + TPB - 1) / TPB);   // 2048

    fused_kernel<<<nblocks, TPB>>>(states, out,
                                   out + off_prod, out + off_align,
                                   out + off_qerr, out + off_fano,
                                   nrows, off_idx,
                                   1.0 / ((double)nrows * 8.0),
                                   1.0 / ((double)B * (double)LL),
                                   nblocks);
}